// round 1
// baseline (speedup 1.0000x reference)
#include <cuda_runtime.h>
#include <math.h>

#define N_NODES 200000
#define C_INN   256
#define C_MID   64
#define KNB     27
#define TILE_R  160
#define NTHREADS 320
#define NBLOCKS (N_NODES / TILE_R)   // 1250 exact
#define BN_EPS  1e-3f

// ---------------- scratch (device globals; no allocations allowed) ----------
__device__ float g_y1[(size_t)N_NODES * C_MID];   // x@W1
__device__ float g_y2[(size_t)N_NODES * C_MID];   // gathered conv out
__device__ float g_y3[(size_t)N_NODES * C_INN];   // h2@W3
// stats layout: [0:64) sum1 [64:128) sq1 [128:192) sum2 [192:256) sq2
//               [256:512) sum3 [512:768) sq3
__device__ float g_stats[768];
__device__ float g_scale1[C_MID], g_shift1[C_MID];
__device__ float g_scale2[C_MID], g_shift2[C_MID];
__device__ float g_scale3[C_INN], g_shift3[C_INN];

// ---------------- small kernels ----------------
__global__ void zero_stats_kernel() {
    int t = threadIdx.x;
    for (int i = t; i < 768; i += 256) g_stats[i] = 0.f;
}

// which: 0 -> BN1, 1 -> BN2, 2 -> BN3
__global__ void finalize_kernel(int which, const float* __restrict__ gamma,
                                const float* __restrict__ beta) {
    int t = threadIdx.x;
    int C       = (which == 2) ? 256 : 64;
    int sum_off = (which == 0) ? 0 : (which == 1) ? 128 : 256;
    int sq_off  = sum_off + C;
    float* scale = (which == 0) ? g_scale1 : (which == 1) ? g_scale2 : g_scale3;
    float* shift = (which == 0) ? g_shift1 : (which == 1) ? g_shift2 : g_shift3;
    if (t < C) {
        const float inv_n = 1.0f / (float)N_NODES;
        float mean = g_stats[sum_off + t] * inv_n;
        float var  = g_stats[sq_off + t] * inv_n - mean * mean;
        float sc   = gamma[t] * rsqrtf(var + BN_EPS);
        scale[t] = sc;
        shift[t] = beta[t] - mean * sc;
    }
}

// ---------------- GEMM1: y1 = x @ W1, fused stats1 ----------------
// tile: 160 nodes x 64 cols, K=256 in 4 chunks of 64
__global__ __launch_bounds__(NTHREADS, 2)
void gemm1_kernel(const float* __restrict__ x, const float* __restrict__ W1) {
    extern __shared__ float sm[];
    float* As   = sm;                    // [64][160] transposed
    float* Bs   = As + 64 * TILE_R;      // [64][64]
    float* s_sum = Bs + 64 * 64;         // [64]
    float* s_sq  = s_sum + 64;           // [64]

    const int t  = threadIdx.x;
    const int n0 = blockIdx.x * TILE_R;
    const int cg = t & 15, rg = t >> 4;      // 16 col-groups x 20 row-groups
    const int c0 = cg * 4, r0 = rg * 8;
    const int r  = t % TILE_R, h = t / TILE_R;   // loader mapping

    float acc[8][4];
    #pragma unroll
    for (int j = 0; j < 8; j++)
        #pragma unroll
        for (int i = 0; i < 4; i++) acc[j][i] = 0.f;

    const float* xrow = x + (size_t)(n0 + r) * C_INN + h * 32;

    for (int kc = 0; kc < 4; kc++) {
        __syncthreads();
        // B chunk: rows [kc*64, kc*64+64) of W1[256][64] -> 4096 floats
        for (int i4 = t; i4 < 1024; i4 += NTHREADS)
            ((float4*)Bs)[i4] = ((const float4*)(W1 + kc * 64 * C_MID))[i4];
        // A chunk transposed
        #pragma unroll
        for (int i = 0; i < 8; i++) {
            float4 v = *(const float4*)(xrow + kc * 64 + i * 4);
            int c = h * 32 + i * 4;
            As[(c + 0) * TILE_R + r] = v.x;
            As[(c + 1) * TILE_R + r] = v.y;
            As[(c + 2) * TILE_R + r] = v.z;
            As[(c + 3) * TILE_R + r] = v.w;
        }
        __syncthreads();
        #pragma unroll 4
        for (int cc = 0; cc < 64; cc++) {
            float4 b4 = *(const float4*)(Bs + cc * 64 + c0);
            float4 a0 = *(const float4*)(As + cc * TILE_R + r0);
            float4 a1 = *(const float4*)(As + cc * TILE_R + r0 + 4);
            float a[8] = {a0.x, a0.y, a0.z, a0.w, a1.x, a1.y, a1.z, a1.w};
            float b[4] = {b4.x, b4.y, b4.z, b4.w};
            #pragma unroll
            for (int j = 0; j < 8; j++)
                #pragma unroll
                for (int i = 0; i < 4; i++) acc[j][i] = fmaf(a[j], b[i], acc[j][i]);
        }
    }

    // store y1
    #pragma unroll
    for (int j = 0; j < 8; j++) {
        float4 v = make_float4(acc[j][0], acc[j][1], acc[j][2], acc[j][3]);
        *(float4*)(g_y1 + (size_t)(n0 + r0 + j) * C_MID + c0) = v;
    }
    // fused stats
    if (t < 64) { s_sum[t] = 0.f; s_sq[t] = 0.f; }
    __syncthreads();
    float ls[4] = {0, 0, 0, 0}, lq[4] = {0, 0, 0, 0};
    #pragma unroll
    for (int j = 0; j < 8; j++)
        #pragma unroll
        for (int i = 0; i < 4; i++) { ls[i] += acc[j][i]; lq[i] += acc[j][i] * acc[j][i]; }
    #pragma unroll
    for (int i = 0; i < 4; i++) {
        atomicAdd(&s_sum[c0 + i], ls[i]);
        atomicAdd(&s_sq[c0 + i], lq[i]);
    }
    __syncthreads();
    if (t < 64) {
        atomicAdd(&g_stats[t], s_sum[t]);
        atomicAdd(&g_stats[64 + t], s_sq[t]);
    }
}

// ---------------- GEMM2: y2[n,d] = sum_k sum_c relu(bn1(y1))[neigh[n,k],c] * W2[k,c,d] ----
__global__ __launch_bounds__(NTHREADS, 2)
void gemm2_kernel(const int* __restrict__ neigh, const float* __restrict__ W2) {
    extern __shared__ float sm[];
    float* As    = sm;                   // [64][160]
    float* Bs    = As + 64 * TILE_R;     // [64][64]
    float* s_sc  = Bs + 64 * 64;         // [64]
    float* s_sh  = s_sc + 64;            // [64]
    float* s_sum = s_sh + 64;            // [64]
    float* s_sq  = s_sum + 64;           // [64]
    int*   s_idx = (int*)(s_sq + 64);    // [160*27]

    const int t  = threadIdx.x;
    const int n0 = blockIdx.x * TILE_R;
    const int cg = t & 15, rg = t >> 4;
    const int c0 = cg * 4, r0 = rg * 8;
    const int r  = t % TILE_R, h = t / TILE_R;

    if (t < 64) { s_sc[t] = g_scale1[t]; s_sh[t] = g_shift1[t]; }
    for (int i = t; i < TILE_R * KNB; i += NTHREADS)
        s_idx[i] = neigh[(size_t)n0 * KNB + i];

    float acc[8][4];
    #pragma unroll
    for (int j = 0; j < 8; j++)
        #pragma unroll
        for (int i = 0; i < 4; i++) acc[j][i] = 0.f;

    for (int k = 0; k < KNB; k++) {
        __syncthreads();    // also covers s_sc/s_idx on k==0
        for (int i4 = t; i4 < 1024; i4 += NTHREADS)
            ((float4*)Bs)[i4] = ((const float4*)(W2 + (size_t)k * 4096))[i4];
        int src = s_idx[r * KNB + k];
        const float4* yrow = (const float4*)(g_y1 + (size_t)src * C_MID + h * 32);
        #pragma unroll
        for (int i = 0; i < 8; i++) {
            float4 v = yrow[i];
            int c = h * 32 + i * 4;
            As[(c + 0) * TILE_R + r] = fmaxf(fmaf(v.x, s_sc[c + 0], s_sh[c + 0]), 0.f);
            As[(c + 1) * TILE_R + r] = fmaxf(fmaf(v.y, s_sc[c + 1], s_sh[c + 1]), 0.f);
            As[(c + 2) * TILE_R + r] = fmaxf(fmaf(v.z, s_sc[c + 2], s_sh[c + 2]), 0.f);
            As[(c + 3) * TILE_R + r] = fmaxf(fmaf(v.w, s_sc[c + 3], s_sh[c + 3]), 0.f);
        }
        __syncthreads();
        #pragma unroll 4
        for (int cc = 0; cc < 64; cc++) {
            float4 b4 = *(const float4*)(Bs + cc * 64 + c0);
            float4 a0 = *(const float4*)(As + cc * TILE_R + r0);
            float4 a1 = *(const float4*)(As + cc * TILE_R + r0 + 4);
            float a[8] = {a0.x, a0.y, a0.z, a0.w, a1.x, a1.y, a1.z, a1.w};
            float b[4] = {b4.x, b4.y, b4.z, b4.w};
            #pragma unroll
            for (int j = 0; j < 8; j++)
                #pragma unroll
                for (int i = 0; i < 4; i++) acc[j][i] = fmaf(a[j], b[i], acc[j][i]);
        }
    }

    #pragma unroll
    for (int j = 0; j < 8; j++) {
        float4 v = make_float4(acc[j][0], acc[j][1], acc[j][2], acc[j][3]);
        *(float4*)(g_y2 + (size_t)(n0 + r0 + j) * C_MID + c0) = v;
    }
    if (t < 64) { s_sum[t] = 0.f; s_sq[t] = 0.f; }
    __syncthreads();
    float ls[4] = {0, 0, 0, 0}, lq[4] = {0, 0, 0, 0};
    #pragma unroll
    for (int j = 0; j < 8; j++)
        #pragma unroll
        for (int i = 0; i < 4; i++) { ls[i] += acc[j][i]; lq[i] += acc[j][i] * acc[j][i]; }
    #pragma unroll
    for (int i = 0; i < 4; i++) {
        atomicAdd(&s_sum[c0 + i], ls[i]);
        atomicAdd(&s_sq[c0 + i], lq[i]);
    }
    __syncthreads();
    if (t < 64) {
        atomicAdd(&g_stats[128 + t], s_sum[t]);
        atomicAdd(&g_stats[192 + t], s_sq[t]);
    }
}

// ---------------- GEMM3: y3 = relu(bn2(y2)) @ W3, tile 160 x 128 (grid.y = 2) ----
__global__ __launch_bounds__(NTHREADS, 2)
void gemm3_kernel(const float* __restrict__ W3) {
    extern __shared__ float sm[];
    float* As    = sm;                  // [64][160]
    float* Bs    = As + 64 * TILE_R;    // [64][128]
    float* s_sc  = Bs + 64 * 128;       // [64]
    float* s_sh  = s_sc + 64;           // [64]
    float* s_sum = s_sh + 64;           // [128]
    float* s_sq  = s_sum + 128;         // [128]

    const int t    = threadIdx.x;
    const int n0   = blockIdx.x * TILE_R;
    const int cblk = blockIdx.y;         // 0 or 1 -> 128-col half
    const int cg = t & 15, rg = t >> 4;  // 16 x 20
    const int c0 = cg * 8, r0 = rg * 8;
    const int r  = t % TILE_R, h = t / TILE_R;

    if (t < 64) { s_sc[t] = g_scale2[t]; s_sh[t] = g_shift2[t]; }
    __syncthreads();

    // B: W3[64][256] columns [cblk*128, +128) -> [64][128]
    for (int i4 = t; i4 < 2048; i4 += NTHREADS) {
        int cc = i4 >> 5, dd = i4 & 31;
        ((float4*)(Bs + cc * 128))[dd] =
            ((const float4*)(W3 + (size_t)cc * C_INN + cblk * 128))[dd];
    }
    // A: bn2+relu(y2) transposed
    {
        const float4* yrow = (const float4*)(g_y2 + (size_t)(n0 + r) * C_MID + h * 32);
        #pragma unroll
        for (int i = 0; i < 8; i++) {
            float4 v = yrow[i];
            int c = h * 32 + i * 4;
            As[(c + 0) * TILE_R + r] = fmaxf(fmaf(v.x, s_sc[c + 0], s_sh[c + 0]), 0.f);
            As[(c + 1) * TILE_R + r] = fmaxf(fmaf(v.y, s_sc[c + 1], s_sh[c + 1]), 0.f);
            As[(c + 2) * TILE_R + r] = fmaxf(fmaf(v.z, s_sc[c + 2], s_sh[c + 2]), 0.f);
            As[(c + 3) * TILE_R + r] = fmaxf(fmaf(v.w, s_sc[c + 3], s_sh[c + 3]), 0.f);
        }
    }
    __syncthreads();

    float acc[8][8];
    #pragma unroll
    for (int j = 0; j < 8; j++)
        #pragma unroll
        for (int i = 0; i < 8; i++) acc[j][i] = 0.f;

    #pragma unroll 2
    for (int cc = 0; cc < 64; cc++) {
        float4 a0 = *(const float4*)(As + cc * TILE_R + r0);
        float4 a1 = *(const float4*)(As + cc * TILE_R + r0 + 4);
        float4 b0 = *(const float4*)(Bs + cc * 128 + c0);
        float4 b1 = *(const float4*)(Bs + cc * 128 + c0 + 4);
        float a[8] = {a0.x, a0.y, a0.z, a0.w, a1.x, a1.y, a1.z, a1.w};
        float b[8] = {b0.x, b0.y, b0.z, b0.w, b1.x, b1.y, b1.z, b1.w};
        #pragma unroll
        for (int j = 0; j < 8; j++)
            #pragma unroll
            for (int i = 0; i < 8; i++) acc[j][i] = fmaf(a[j], b[i], acc[j][i]);
    }

    // store y3
    #pragma unroll
    for (int j = 0; j < 8; j++) {
        float* dst = g_y3 + (size_t)(n0 + r0 + j) * C_INN + cblk * 128 + c0;
        *(float4*)(dst)     = make_float4(acc[j][0], acc[j][1], acc[j][2], acc[j][3]);
        *(float4*)(dst + 4) = make_float4(acc[j][4], acc[j][5], acc[j][6], acc[j][7]);
    }
    // fused stats3 (128 local cols)
    if (t < 128) { s_sum[t] = 0.f; s_sq[t] = 0.f; }
    __syncthreads();
    float ls[8] = {0, 0, 0, 0, 0, 0, 0, 0}, lq[8] = {0, 0, 0, 0, 0, 0, 0, 0};
    #pragma unroll
    for (int j = 0; j < 8; j++)
        #pragma unroll
        for (int i = 0; i < 8; i++) { ls[i] += acc[j][i]; lq[i] += acc[j][i] * acc[j][i]; }
    #pragma unroll
    for (int i = 0; i < 8; i++) {
        atomicAdd(&s_sum[c0 + i], ls[i]);
        atomicAdd(&s_sq[c0 + i], lq[i]);
    }
    __syncthreads();
    if (t < 128) {
        atomicAdd(&g_stats[256 + cblk * 128 + t], s_sum[t]);
        atomicAdd(&g_stats[512 + cblk * 128 + t], s_sq[t]);
    }
}

// ---------------- epilogue: out = relu(bn3(y3) + x) ----------------
__global__ void epilogue_kernel(const float* __restrict__ x, float* __restrict__ out) {
    size_t i4 = (size_t)blockIdx.x * blockDim.x + threadIdx.x;
    if (i4 >= (size_t)N_NODES * (C_INN / 4)) return;
    int c = ((int)(i4 & 63)) << 2;   // channel of .x
    float4 y  = ((const float4*)g_y3)[i4];
    float4 xi = ((const float4*)x)[i4];
    float4 o;
    o.x = fmaxf(fmaf(y.x, g_scale3[c + 0], g_shift3[c + 0]) + xi.x, 0.f);
    o.y = fmaxf(fmaf(y.y, g_scale3[c + 1], g_shift3[c + 1]) + xi.y, 0.f);
    o.z = fmaxf(fmaf(y.z, g_scale3[c + 2], g_shift3[c + 2]) + xi.z, 0.f);
    o.w = fmaxf(fmaf(y.w, g_scale3[c + 3], g_shift3[c + 3]) + xi.w, 0.f);
    ((float4*)out)[i4] = o;
}

// ---------------- launch ----------------
#define SMEM1 ((64 * TILE_R + 64 * 64 + 128) * 4)
#define SMEM2 ((64 * TILE_R + 64 * 64 + 256) * 4 + TILE_R * KNB * 4)
#define SMEM3 ((64 * TILE_R + 64 * 128 + 384) * 4)

extern "C" void kernel_launch(void* const* d_in, const int* in_sizes, int n_in,
                              void* d_out, int out_size) {
    const float* x     = (const float*)d_in[0];
    const int*   neigh = (const int*)d_in[1];
    // d_in[2] = depth (unused)
    const float* W1 = (const float*)d_in[3];
    const float* g1 = (const float*)d_in[4];
    const float* b1 = (const float*)d_in[5];
    const float* W2 = (const float*)d_in[6];
    const float* g2 = (const float*)d_in[7];
    const float* b2 = (const float*)d_in[8];
    const float* W3 = (const float*)d_in[9];
    const float* g3 = (const float*)d_in[10];
    const float* b3 = (const float*)d_in[11];
    float* out = (float*)d_out;

    cudaFuncSetAttribute(gemm1_kernel, cudaFuncAttributeMaxDynamicSharedMemorySize, SMEM1);
    cudaFuncSetAttribute(gemm2_kernel, cudaFuncAttributeMaxDynamicSharedMemorySize, SMEM2);
    cudaFuncSetAttribute(gemm3_kernel, cudaFuncAttributeMaxDynamicSharedMemorySize, SMEM3);

    zero_stats_kernel<<<1, 256>>>();
    gemm1_kernel<<<NBLOCKS, NTHREADS, SMEM1>>>(x, W1);
    finalize_kernel<<<1, 256>>>(0, g1, b1);
    gemm2_kernel<<<NBLOCKS, NTHREADS, SMEM2>>>(neigh, W2);
    finalize_kernel<<<1, 256>>>(1, g2, b2);
    dim3 grid3(NBLOCKS, 2);
    gemm3_kernel<<<grid3, NTHREADS, SMEM3>>>(W3);
    finalize_kernel<<<1, 256>>>(2, g3, b3);
    epilogue_kernel<<<(N_NODES * (C_INN / 4) + 255) / 256, 256>>>(x, out);
}